// round 15
// baseline (speedup 1.0000x reference)
#include <cuda_runtime.h>
#include <cuda_fp16.h>
#include <cstdint>

#define NN 100000
#define NE 250000
#define D  300
#define LDH 320
#define LDHID 640
#define NL 5

// ---------------- device-global scratch ------------------------------------
__device__ float  g_h  [(size_t)NN * LDH];
__device__ __half g_agg_hi[(size_t)NN * LDH];
__device__ __half g_agg_lo[(size_t)NN * LDH];
__device__ __half g_hid_hi[(size_t)NN * LDHID];
__device__ __half g_hid_lo[(size_t)NN * LDHID];
__device__ float  g_h2 [(size_t)NN * LDH];
__device__ __half g_w1hi[NL * 640 * LDH];
__device__ __half g_w1lo[NL * 640 * LDH];
__device__ __half g_w2hi[NL * 384 * LDHID];
__device__ __half g_w2lo[NL * 384 * LDHID];
__device__ float  g_b1p[NL * 640];
__device__ float  g_b2p[NL * LDH];
__device__ int    g_rowptr[NN + 1];
__device__ int    g_cnt[NN];
__device__ int    g_src[NE];
__device__ unsigned char g_ec[NE];
__device__ float  g_colsum[LDH], g_colsq[LDH], g_scale[LDH], g_shift[LDH];

// ---------------- PTX helpers ----------------------------------------------
__device__ __forceinline__ uint32_t smem_u32(const void* p) {
    uint32_t a;
    asm("{ .reg .u64 t; cvta.to.shared.u64 t, %1; cvt.u32.u64 %0, t; }"
        : "=r"(a) : "l"(p));
    return a;
}
__device__ __forceinline__ void cp16(uint32_t dst, const void* src, int srcbytes) {
    asm volatile("cp.async.cg.shared.global [%0], [%1], 16, %2;"
                 :: "r"(dst), "l"(src), "r"(srcbytes) : "memory");
}
#define CP_COMMIT() asm volatile("cp.async.commit_group;" ::: "memory")
#define CP_WAIT1()  asm volatile("cp.async.wait_group 1;" ::: "memory")
#define CP_WAIT0()  asm volatile("cp.async.wait_group 0;" ::: "memory")

__device__ __forceinline__ void mma_h(float* c, const uint32_t* a,
                                      uint32_t b0, uint32_t b1) {
    asm volatile(
        "mma.sync.aligned.m16n8k16.row.col.f32.f16.f16.f32 "
        "{%0,%1,%2,%3}, {%4,%5,%6,%7}, {%8,%9}, {%0,%1,%2,%3};"
        : "+f"(c[0]), "+f"(c[1]), "+f"(c[2]), "+f"(c[3])
        : "r"(a[0]), "r"(a[1]), "r"(a[2]), "r"(a[3]), "r"(b0), "r"(b1));
}
__device__ __forceinline__ void ldsm4(uint32_t& r0, uint32_t& r1,
                                      uint32_t& r2, uint32_t& r3, uint32_t addr) {
    asm volatile("ldmatrix.sync.aligned.m8n8.x4.shared.b16 {%0,%1,%2,%3}, [%4];"
                 : "=r"(r0), "=r"(r1), "=r"(r2), "=r"(r3) : "r"(addr));
}

__device__ __forceinline__ void split_h(float v, __half& hi, __half& lo) {
    hi = __float2half(v);
    lo = __float2half(v - __half2float(hi));
}

// ---------------- 3-term fp16 split GEMM: C = A(MxK)*B(NxK)^T + bias --------
// (unchanged from R14: 3-stage single-sync pipeline, XOR swizzle, 2Mx4N warps)
#define SROW 64                          // smem row stride bytes (no pad)
#define TILE_B 8192                      // 128 rows x 64 B
#define STAGE_B (4 * TILE_B)             // Ah, Al, Bh, Bl = 32768
#define GEMM_SMEM (3 * STAGE_B)          // 98304

__global__ __launch_bounds__(256, 2)
void hgemm_kernel(const __half* __restrict__ Ahi, const __half* __restrict__ Alo, int lda,
                  const __half* __restrict__ Bhi, const __half* __restrict__ Blo, int ldb,
                  float* __restrict__ Cf, __half* __restrict__ Chi, __half* __restrict__ Clo,
                  int ldc, const float* __restrict__ bias,
                  int M, int Npad, int nks, int outmode, int stats) {
    extern __shared__ uint32_t smu[];
    uint32_t sbase = smem_u32(smu);
    int tid = threadIdx.x;
    int wid = tid >> 5, lane = tid & 31;
    int warp_m = wid & 1, warp_n = wid >> 1;     // 2 x 4
    int g = lane >> 2, t = lane & 3;

    int m0 = blockIdx.y * 128;
    int n0 = blockIdx.x * 128;
    bool active = (warp_n * 32) < (Npad - n0);   // warp-granular N tail
    int nch = (nks + 1) >> 1;                    // number of 32-wide chunks

    float acc[4][4][4];
#pragma unroll
    for (int i = 0; i < 4; i++)
#pragma unroll
        for (int j = 0; j < 4; j++)
#pragma unroll
            for (int r = 0; r < 4; r++) acc[i][j][r] = 0.f;

    int la_row = warp_m * 64 + (lane & 15);
    int a_b = lane >> 4;
    int a_sw = (la_row >> 1) & 3;
    int lb_row = warp_n * 32 + (lane & 7) + ((lane >> 4) * 8);
    int b_b = (lane >> 3) & 1;
    int b_sw = (lb_row >> 1) & 3;

#define LOAD_CHUNK(slot, kc) do {                                             \
    uint32_t st = sbase + (slot) * STAGE_B;                                   \
    _Pragma("unroll")                                                         \
    for (int it = 0; it < 2; it++) {                                          \
        int u = it * 256 + tid;                                               \
        int row = u >> 2, seg = u & 3;                                        \
        uint32_t so = (uint32_t)(row * SROW + ((seg ^ ((row >> 1) & 3)) * 16)); \
        int gr = m0 + row;                                                    \
        bool va = gr < M;                                                     \
        size_t aoff = (size_t)(va ? gr : 0) * lda + (kc) * 32 + seg * 8;      \
        cp16(st + so, Ahi + aoff, va ? 16 : 0);                               \
        cp16(st + TILE_B + so, Alo + aoff, va ? 16 : 0);                      \
        size_t boff = (size_t)(n0 + row) * ldb + (kc) * 32 + seg * 8;         \
        cp16(st + 2 * TILE_B + so, Bhi + boff, 16);                           \
        cp16(st + 3 * TILE_B + so, Blo + boff, 16);                           \
    }                                                                         \
} while (0)

#define DO_KS(ks) do {                                                        \
    uint32_t aseg = (uint32_t)((((ks) * 2 + a_b) ^ a_sw) * 16);               \
    uint32_t bseg = (uint32_t)((((ks) * 2 + b_b) ^ b_sw) * 16);               \
    uint32_t ah[4][4], al[4][4];                                              \
    _Pragma("unroll")                                                         \
    for (int i = 0; i < 4; i++) {                                             \
        uint32_t off = (uint32_t)((la_row + i * 16) * SROW) + aseg;           \
        ldsm4(ah[i][0], ah[i][1], ah[i][2], ah[i][3], tAh + off);             \
        ldsm4(al[i][0], al[i][1], al[i][2], al[i][3], tAl + off);             \
    }                                                                         \
    uint32_t bh[4][2], bl[4][2];                                              \
    _Pragma("unroll")                                                         \
    for (int jj = 0; jj < 2; jj++) {                                          \
        uint32_t off = (uint32_t)((lb_row + jj * 16) * SROW) + bseg;          \
        ldsm4(bh[2 * jj][0], bh[2 * jj][1], bh[2 * jj + 1][0], bh[2 * jj + 1][1], tBh + off); \
        ldsm4(bl[2 * jj][0], bl[2 * jj][1], bl[2 * jj + 1][0], bl[2 * jj + 1][1], tBl + off); \
    }                                                                         \
    _Pragma("unroll")                                                         \
    for (int j = 0; j < 4; j++) {                                             \
        _Pragma("unroll")                                                     \
        for (int i = 0; i < 4; i++) {                                         \
            mma_h(acc[i][j], ah[i], bh[j][0], bh[j][1]);                      \
            mma_h(acc[i][j], ah[i], bl[j][0], bl[j][1]);                      \
            mma_h(acc[i][j], al[i], bh[j][0], bh[j][1]);                      \
        }                                                                     \
    }                                                                         \
} while (0)

    LOAD_CHUNK(0, 0);
    CP_COMMIT();
    if (nch > 1) LOAD_CHUNK(1, 1);
    CP_COMMIT();

    int cs = 0;
    int ls = 2;
    for (int k = 0; k < nch; k++) {
        if (k + 1 < nch) { CP_WAIT1(); } else { CP_WAIT0(); }
        __syncthreads();
        if (k + 2 < nch) {
            LOAD_CHUNK(ls, k + 2);
            CP_COMMIT();
        }
        uint32_t st = sbase + cs * STAGE_B;
        uint32_t tAh = st, tAl = st + TILE_B;
        uint32_t tBh = st + 2 * TILE_B, tBl = st + 3 * TILE_B;
        if (active) {
            DO_KS(0);
            if (2 * k + 2 <= nks) {
                DO_KS(1);
            }
        }
        cs = (cs == 2) ? 0 : cs + 1;
        ls = (ls == 2) ? 0 : ls + 1;
    }
#undef DO_KS
#undef LOAD_CHUNK

    if (active) {
        float csum[4][2], csq[4][2];
#pragma unroll
        for (int j = 0; j < 4; j++) {
            csum[j][0] = csum[j][1] = 0.f;
            csq[j][0] = csq[j][1] = 0.f;
        }
#pragma unroll
        for (int i = 0; i < 4; i++) {
            int row = m0 + warp_m * 64 + i * 16 + g;
#pragma unroll
            for (int j = 0; j < 4; j++) {
                int col = n0 + warp_n * 32 + j * 8 + 2 * t;
                if (col >= Npad) continue;
                float2 bv = *(const float2*)(bias + col);
#pragma unroll
                for (int h = 0; h < 2; h++) {
                    int r = row + h * 8;
                    if (r >= M) continue;
                    float vx = acc[i][j][2 * h + 0] + bv.x;
                    float vy = acc[i][j][2 * h + 1] + bv.y;
                    if (outmode == 1) {
                        vx = fmaxf(vx, 0.f); vy = fmaxf(vy, 0.f);
                        __half hx, lx, hy, ly;
                        split_h(vx, hx, lx);
                        split_h(vy, hy, ly);
                        *(half2*)(Chi + (size_t)r * ldc + col) = __halves2half2(hx, hy);
                        *(half2*)(Clo + (size_t)r * ldc + col) = __halves2half2(lx, ly);
                    } else {
                        float2 v; v.x = vx; v.y = vy;
                        *(float2*)(Cf + (size_t)r * ldc + col) = v;
                        if (stats) {
                            csum[j][0] += vx; csq[j][0] += vx * vx;
                            csum[j][1] += vy; csq[j][1] += vy * vy;
                        }
                    }
                }
            }
        }
        if (stats) {
#pragma unroll
            for (int j = 0; j < 4; j++)
#pragma unroll
                for (int h = 0; h < 2; h++) {
#pragma unroll
                    for (int off = 16; off >= 4; off >>= 1) {
                        csum[j][h] += __shfl_down_sync(0xffffffff, csum[j][h], off);
                        csq[j][h]  += __shfl_down_sync(0xffffffff, csq[j][h], off);
                    }
                }
            if (lane < 4) {
#pragma unroll
                for (int j = 0; j < 4; j++)
#pragma unroll
                    for (int h = 0; h < 2; h++) {
                        int col = n0 + warp_n * 32 + j * 8 + 2 * lane + h;
                        if (col < D) {
                            atomicAdd(&g_colsum[col], csum[j][h]);
                            atomicAdd(&g_colsq[col], csq[j][h]);
                        }
                    }
            }
        }
    }
}

// ---------------- input embedding -------------------------------------------
__global__ __launch_bounds__(LDH)
void init_h_kernel(const int* __restrict__ x,
                   const float* __restrict__ t1,
                   const float* __restrict__ t2) {
    int f = threadIdx.x;
    size_t i = blockIdx.x;
    float v = 0.f;
    if (f < D) {
        int a = x[2 * i];
        int b = x[2 * i + 1];
        v = t1[a * D + f] + t2[b * D + f];
    }
    g_h[i * LDH + f] = v;
}

// ---------------- weight / bias packing (fp32 -> fp16 hi/lo, padded) --------
__global__ __launch_bounds__(LDH)
void pack_w1_kernel(const float* __restrict__ w1) {
    int k = threadIdx.x;
    int r = blockIdx.x;
    int l = r / 640, row = r % 640;
    float v = 0.f;
    if (row < 600 && k < D) v = w1[(size_t)(l * 600 + row) * D + k];
    __half hi, lo;
    split_h(v, hi, lo);
    g_w1hi[(size_t)r * LDH + k] = hi;
    g_w1lo[(size_t)r * LDH + k] = lo;
}
__global__ __launch_bounds__(LDHID)
void pack_w2_kernel(const float* __restrict__ w2) {
    int k = threadIdx.x;
    int r = blockIdx.x;
    int l = r / 384, row = r % 384;
    float v = 0.f;
    if (row < D && k < 600) v = w2[(size_t)(l * D + row) * 600 + k];
    __half hi, lo;
    split_h(v, hi, lo);
    g_w2hi[(size_t)r * LDHID + k] = hi;
    g_w2lo[(size_t)r * LDHID + k] = lo;
}
__global__ __launch_bounds__(256)
void pack_b1_kernel(const float* __restrict__ b1) {
    int i = blockIdx.x * 256 + threadIdx.x;
    if (i >= NL * 640) return;
    int l = i / 640, c = i % 640;
    g_b1p[i] = (c < 600) ? b1[l * 600 + c] : 0.f;
}
__global__ __launch_bounds__(256)
void pack_b2_kernel(const float* __restrict__ b2) {
    int i = blockIdx.x * 256 + threadIdx.x;
    if (i >= NL * LDH) return;
    int l = i / LDH, c = i % LDH;
    g_b2p[i] = (c < D) ? b2[l * D + c] : 0.f;
}

// ---------------- CSR build (dst-sorted) ------------------------------------
__global__ __launch_bounds__(256)
void zero_cnt_kernel() {
    int i = blockIdx.x * blockDim.x + threadIdx.x;
    if (i < NN) g_cnt[i] = 0;
}
__global__ __launch_bounds__(256)
void hist_kernel(const int* __restrict__ ei) {
    int e = blockIdx.x * blockDim.x + threadIdx.x;
    if (e < NE) atomicAdd(&g_cnt[ei[NE + e]], 1);
}
__global__ __launch_bounds__(512)
void scan_kernel() {
    __shared__ int s[512];
    const int CH = (NN + 511) / 512;
    int t = threadIdx.x;
    int base = t * CH;
    int sum = 0;
#pragma unroll 1
    for (int i = 0; i < CH; i++) {
        int idx = base + i;
        if (idx < NN) sum += g_cnt[idx];
    }
    s[t] = sum;
    __syncthreads();
    for (int off = 1; off < 512; off <<= 1) {
        int v = (t >= off) ? s[t - off] : 0;
        __syncthreads();
        s[t] += v;
        __syncthreads();
    }
    int run = s[t] - sum;
#pragma unroll 1
    for (int i = 0; i < CH; i++) {
        int idx = base + i;
        if (idx < NN) { g_rowptr[idx] = run; run += g_cnt[idx]; }
    }
    if (t == 511) g_rowptr[NN] = s[511];
}
__global__ __launch_bounds__(256)
void scatter_kernel(const int* __restrict__ ei,
                    const int* __restrict__ ea) {
    int e = blockIdx.x * blockDim.x + threadIdx.x;
    if (e >= NE) return;
    int srcv = ei[e];
    int dstv = ei[NE + e];
    int pos = g_rowptr[dstv] + atomicAdd(&g_cnt[dstv], 1);
    g_src[pos] = srcv;
    g_ec[pos] = (unsigned char)(ea[2 * e] * 3 + ea[2 * e + 1]);
}

// ---------------- gather-aggregate with fused BN+ReLU (float4, unroll 2) ----
template <int TRANSFORM>
__global__ __launch_bounds__(256)
void agg_kernel(const float* __restrict__ X,
                const float* __restrict__ e1,
                const float* __restrict__ e2) {
    __shared__ float etab[18 * D];
    int tid = threadIdx.x;
    for (int idx = tid; idx < 18 * D; idx += 256) {
        int c = idx / D, f = idx - c * D;
        etab[idx] = e1[(c / 3) * D + f] + e2[(c % 3) * D + f];
    }
    __syncthreads();
    int warp = tid >> 5, lane = tid & 31;
    int node = blockIdx.x * 8 + warp;
    if (node >= NN) return;

    int f0 = lane * 4;                   // segment j covers f0 + 128*j
    bool m2 = (f0 + 256) < D;            // lanes 0..10 have a valid 3rd float4

    float4 sc4[3], sh4[3];
    if (TRANSFORM) {
        sc4[0] = *(const float4*)(g_scale + f0);
        sh4[0] = *(const float4*)(g_shift + f0);
        sc4[1] = *(const float4*)(g_scale + f0 + 128);
        sh4[1] = *(const float4*)(g_shift + f0 + 128);
        if (m2) {
            sc4[2] = *(const float4*)(g_scale + f0 + 256);
            sh4[2] = *(const float4*)(g_shift + f0 + 256);
        }
    }

#define TRF(v, q) do { if (TRANSFORM) {                                       \
    v.x = fmaxf(fmaf(v.x, sc4[q].x, sh4[q].x), 0.f);                          \
    v.y = fmaxf(fmaf(v.y, sc4[q].y, sh4[q].y), 0.f);                          \
    v.z = fmaxf(fmaf(v.z, sc4[q].z, sh4[q].z), 0.f);                          \
    v.w = fmaxf(fmaf(v.w, sc4[q].w, sh4[q].w), 0.f); } } while (0)
#define ACC4(a, v, e) do { a.x += v.x + e.x; a.y += v.y + e.y;                \
                           a.z += v.z + e.z; a.w += v.w + e.w; } while (0)

    const float4 Z = make_float4(0.f, 0.f, 0.f, 0.f);
    float4 a0 = Z, a1 = Z, a2 = Z;
    const float* etS = etab + 12 * D;    // self-loop edge code 12

    // self loop
    {
        const float* hr = X + (size_t)node * LDH;
        float4 v0 = *(const float4*)(hr + f0);
        float4 v1 = *(const float4*)(hr + f0 + 128);
        float4 v2 = m2 ? *(const float4*)(hr + f0 + 256) : Z;
        TRF(v0, 0); TRF(v1, 1); TRF(v2, 2);
        float4 e0 = *(const float4*)(etS + f0);
        float4 e1v = *(const float4*)(etS + f0 + 128);
        float4 e2v = m2 ? *(const float4*)(etS + f0 + 256) : Z;
        ACC4(a0, v0, e0); ACC4(a1, v1, e1v); ACC4(a2, v2, e2v);
    }

    int e = g_rowptr[node];
    int end = g_rowptr[node + 1];
#pragma unroll 1
    for (; e + 1 < end; e += 2) {
        int s0 = g_src[e], s1 = g_src[e + 1];
        int c0 = (int)g_ec[e], c1 = (int)g_ec[e + 1];
        const float* p0 = X + (size_t)s0 * LDH;
        const float* p1 = X + (size_t)s1 * LDH;
        float4 u0 = *(const float4*)(p0 + f0);
        float4 u1 = *(const float4*)(p0 + f0 + 128);
        float4 u2 = m2 ? *(const float4*)(p0 + f0 + 256) : Z;
        float4 w0 = *(const float4*)(p1 + f0);
        float4 w1 = *(const float4*)(p1 + f0 + 128);
        float4 w2 = m2 ? *(const float4*)(p1 + f0 + 256) : Z;
        TRF(u0, 0); TRF(u1, 1); TRF(u2, 2);
        TRF(w0, 0); TRF(w1, 1); TRF(w2, 2);
        const float* E0 = etab + c0 * D;
        const float* E1 = etab + c1 * D;
        float4 x0 = *(const float4*)(E0 + f0);
        float4 x1 = *(const float4*)(E0 + f0 + 128);
        float4 x2 = m2 ? *(const float4*)(E0 + f0 + 256) : Z;
        ACC4(a0, u0, x0); ACC4(a1, u1, x1); ACC4(a2, u2, x2);
        float4 y0 = *(const float4*)(E1 + f0);
        float4 y1 = *(const float4*)(E1 + f0 + 128);
        float4 y2 = m2 ? *(const float4*)(E1 + f0 + 256) : Z;
        ACC4(a0, w0, y0); ACC4(a1, w1, y1); ACC4(a2, w2, y2);
    }
    if (e < end) {
        int s0 = g_src[e];
        int c0 = (int)g_ec[e];
        const float* p0 = X + (size_t)s0 * LDH;
        float4 u0 = *(const float4*)(p0 + f0);
        float4 u1 = *(const float4*)(p0 + f0 + 128);
        float4 u2 = m2 ? *(const float4*)(p0 + f0 + 256) : Z;
        TRF(u0, 0); TRF(u1, 1); TRF(u2, 2);
        const float* E0 = etab + c0 * D;
        float4 x0 = *(const float4*)(E0 + f0);
        float4 x1 = *(const float4*)(E0 + f0 + 128);
        float4 x2 = m2 ? *(const float4*)(E0 + f0 + 256) : Z;
        ACC4(a0, u0, x0); ACC4(a1, u1, x1); ACC4(a2, u2, x2);
    }
#undef TRF
#undef ACC4

    // split to fp16 hi/lo and store
    size_t base = (size_t)node * LDH;
#define STORE4(v, foff) do {                                                  \
    __half hx, lx, hy, ly, hz, lz, hw, lw;                                    \
    split_h(v.x, hx, lx); split_h(v.y, hy, ly);                               \
    split_h(v.z, hz, lz); split_h(v.w, hw, lw);                               \
    *(half2*)(g_agg_hi + base + (foff))     = __halves2half2(hx, hy);         \
    *(half2*)(g_agg_hi + base + (foff) + 2) = __halves2half2(hz, hw);         \
    *(half2*)(g_agg_lo + base + (foff))     = __halves2half2(lx, ly);         \
    *(half2*)(g_agg_lo + base + (foff) + 2) = __halves2half2(lz, lw);         \
} while (0)
    STORE4(a0, f0);
    STORE4(a1, f0 + 128);
    if (m2) {
        STORE4(a2, f0 + 256);
    } else if (f0 + 256 < LDH) {
        // zero the pad cols [300, 320)
        STORE4(Z, f0 + 256);
    }
#undef STORE4
}

// ---------------- BatchNorm helpers -----------------------------------------
__global__ __launch_bounds__(LDH)
void zero_stats_kernel() {
    int f = threadIdx.x;
    g_colsum[f] = 0.f; g_colsq[f] = 0.f;
}
__global__ __launch_bounds__(LDH)
void bn_final_kernel(const float* __restrict__ gamma,
                     const float* __restrict__ beta) {
    int f = threadIdx.x;
    if (f < D) {
        float inv_n = 1.f / (float)NN;
        float mean = g_colsum[f] * inv_n;
        float var  = g_colsq[f] * inv_n - mean * mean;
        float sc = gamma[f] * rsqrtf(var + 1e-5f);
        g_scale[f] = sc;
        g_shift[f] = beta[f] - mean * sc;
    }
    g_colsum[f] = 0.f;
    g_colsq[f] = 0.f;
}
__global__ __launch_bounds__(LDH)
void bn_apply_out_kernel(const float* __restrict__ X, float* __restrict__ out) {
    int f = threadIdx.x;
    if (f >= D) return;
    size_t i = blockIdx.x;
    out[i * (size_t)D + f] = X[i * LDH + f] * g_scale[f] + g_shift[f];
}

// ---------------- launch ----------------------------------------------------
extern "C" void kernel_launch(void* const* d_in, const int* in_sizes, int n_in,
                              void* d_out, int out_size) {
    const int*   x     = (const int*)d_in[0];
    const int*   ei    = (const int*)d_in[1];
    const int*   ea    = (const int*)d_in[2];
    const float* xe1   = (const float*)d_in[3];
    const float* xe2   = (const float*)d_in[4];
    const float* ee1   = (const float*)d_in[5];
    const float* ee2   = (const float*)d_in[6];
    const float* w1    = (const float*)d_in[7];
    const float* b1    = (const float*)d_in[8];
    const float* w2    = (const float*)d_in[9];
    const float* b2    = (const float*)d_in[10];
    const float* gamma = (const float*)d_in[11];
    const float* beta  = (const float*)d_in[12];
    float* out = (float*)d_out;

    float *h, *h2, *b1p, *b2p;
    __half *agg_hi, *agg_lo, *hid_hi, *hid_lo, *w1hi, *w1lo, *w2hi, *w2lo;
    cudaGetSymbolAddress((void**)&h,      g_h);
    cudaGetSymbolAddress((void**)&h2,     g_h2);
    cudaGetSymbolAddress((void**)&agg_hi, g_agg_hi);
    cudaGetSymbolAddress((void**)&agg_lo, g_agg_lo);
    cudaGetSymbolAddress((void**)&hid_hi, g_hid_hi);
    cudaGetSymbolAddress((void**)&hid_lo, g_hid_lo);
    cudaGetSymbolAddress((void**)&w1hi,   g_w1hi);
    cudaGetSymbolAddress((void**)&w1lo,   g_w1lo);
    cudaGetSymbolAddress((void**)&w2hi,   g_w2hi);
    cudaGetSymbolAddress((void**)&w2lo,   g_w2lo);
    cudaGetSymbolAddress((void**)&b1p,    g_b1p);
    cudaGetSymbolAddress((void**)&b2p,    g_b2p);

    static int smem_set = 0;
    if (!smem_set) {
        cudaFuncSetAttribute(hgemm_kernel,
                             cudaFuncAttributeMaxDynamicSharedMemorySize, GEMM_SMEM);
        smem_set = 1;
    }

    // prep
    pack_w1_kernel<<<NL * 640, LDH>>>(w1);
    pack_w2_kernel<<<NL * 384, LDHID>>>(w2);
    pack_b1_kernel<<<(NL * 640 + 255) / 256, 256>>>(b1);
    pack_b2_kernel<<<(NL * LDH + 255) / 256, 256>>>(b2);
    zero_stats_kernel<<<1, LDH>>>();
    init_h_kernel<<<NN, LDH>>>(x, xe1, xe2);

    // CSR build
    zero_cnt_kernel<<<(NN + 255) / 256, 256>>>();
    hist_kernel<<<(NE + 255) / 256, 256>>>(ei);
    scan_kernel<<<1, 512>>>();
    zero_cnt_kernel<<<(NN + 255) / 256, 256>>>();
    scatter_kernel<<<(NE + 255) / 256, 256>>>(ei, ea);

    const int MT = (NN + 127) / 128;   // 782
    for (int l = 0; l < NL; l++) {
        if (l == 0)
            agg_kernel<0><<<(NN + 7) / 8, 256>>>(h, ee1 + l * 6 * D, ee2 + l * 3 * D);
        else
            agg_kernel<1><<<(NN + 7) / 8, 256>>>(h2, ee1 + l * 6 * D, ee2 + l * 3 * D);

        // GEMM1: N 608 (warp-granular tail), K 19 k16-steps (=304, true 300)
        hgemm_kernel<<<dim3(5, MT), 256, GEMM_SMEM>>>(
            agg_hi, agg_lo, LDH,
            w1hi + (size_t)l * 640 * LDH, w1lo + (size_t)l * 640 * LDH, LDH,
            nullptr, hid_hi, hid_lo, LDHID, b1p + l * 640,
            NN, 608, 19, 1, 0);

        // GEMM2: N 320 (warp-granular tail), K 38 k16-steps (=608), stats fused
        hgemm_kernel<<<dim3(3, MT), 256, GEMM_SMEM>>>(
            hid_hi, hid_lo, LDHID,
            w2hi + (size_t)l * 384 * LDHID, w2lo + (size_t)l * 384 * LDHID, LDHID,
            h2, nullptr, nullptr, LDH, b2p + l * LDH,
            NN, 320, 38, 0, 1);

        bn_final_kernel<<<1, LDH>>>(gamma + l * D, beta + l * D);

        if (l == NL - 1)
            bn_apply_out_kernel<<<NN, LDH>>>(h2, out);
    }
}